// round 12
// baseline (speedup 1.0000x reference)
#include <cuda_runtime.h>
#include <cstdint>

#define NC      32
#define NSTEPS  32
#define DDIM    30
#define BLOCK   128
#define PPT     8     // independent chains per thread; grid = 2048 blocks

__global__ __launch_bounds__(BLOCK)
void cpab_kernel(const float* __restrict__ points,
                 const float* __restrict__ theta,
                 const float* __restrict__ basis,
                 float* __restrict__ out,
                 int n_points)
{
    __shared__ float s0[NC];
    __shared__ float s1[NC];

    const int t    = blockIdx.y;
    const int tid  = threadIdx.x;
    const int lane = tid & 31;

    // --- 32 per-cell step transforms for this theta ---
    if (tid < NC) {
        const float dT = 1.0f / (float)NSTEPS;
        const float* __restrict__ ba = basis + (2 * tid)     * DDIM;
        const float* __restrict__ bb = basis + (2 * tid + 1) * DDIM;
        const float* __restrict__ th = theta + t * DDIM;
        float a = 0.0f, b = 0.0f;
        #pragma unroll
        for (int j = 0; j < DDIM; ++j) {
            float tj = th[j];
            a = fmaf(ba[j], tj, a);
            b = fmaf(bb[j], tj, b);
        }
        a *= dT;
        b *= dT;
        float ea  = expf(a);
        float phi = (fabsf(a) < 1e-6f) ? (1.0f + 0.5f * a) : (expm1f(a) / a);
        s0[tid] = ea;
        s1[tid] = b * phi;
    }
    __syncthreads();

    // Table lives in registers: lane l holds cell l's transform.
    const float T0 = s0[lane];
    const float T1 = s1[lane];

    // --- Main integration: 8 independent chains per thread ---
    // Block tile is contiguous: 1024 floats starting at blockIdx.x*1024.
    // Thread tid handles elements tid*8 .. tid*8+7 via two float4 loads
    // (16B-aligned since n_points is a multiple of BLOCK*PPT here; guarded
    // fallback for ragged sizes).
    const int tile = blockIdx.x * (BLOCK * PPT);
    const int base = tile + tid * PPT;

    float x[PPT];
    if (base + PPT <= n_points) {
        const float4* p4 = (const float4*)(points + base);
        float4 a0 = __ldg(&p4[0]);
        float4 a1 = __ldg(&p4[1]);
        x[0] = a0.x; x[1] = a0.y; x[2] = a0.z; x[3] = a0.w;
        x[4] = a1.x; x[5] = a1.y; x[6] = a1.z; x[7] = a1.w;
    } else {
        #pragma unroll
        for (int k = 0; k < PPT; ++k) {
            int idx = base + k;
            x[k] = (idx < n_points) ? points[idx] : 0.0f;
        }
    }

    #pragma unroll 4
    for (int s = 0; s < NSTEPS; ++s) {
        #pragma unroll
        for (int k = 0; k < PPT; ++k) {
            // bits = 0x4B000000 + floor(x*32), exact (RZ fma, positive sum).
            // Low 5 bits == cell index; shfl wraps srcLane mod 32.
            int bi = (int)__float_as_uint(__fmaf_rz(x[k], 32.0f, 8388608.0f));
            bi = max(bi, 0x4B000000);          // x < 0  -> cell 0
            bi = min(bi, 0x4B00001F);          // x >= 1 -> cell 31
            float t0 = __shfl_sync(0xFFFFFFFFu, T0, bi);
            float t1 = __shfl_sync(0xFFFFFFFFu, T1, bi);
            x[k] = fmaf(t0, x[k], t1);
        }
    }

    float* __restrict__ o = out + (size_t)t * (size_t)n_points;
    if (base + PPT <= n_points) {
        float4 r0 = make_float4(x[0], x[1], x[2], x[3]);
        float4 r1 = make_float4(x[4], x[5], x[6], x[7]);
        float4* o4 = (float4*)(o + base);
        __stcs(&o4[0], r0);
        __stcs(&o4[1], r1);
    } else {
        #pragma unroll
        for (int k = 0; k < PPT; ++k) {
            int idx = base + k;
            if (idx < n_points) o[idx] = x[k];
        }
    }
}

extern "C" void kernel_launch(void* const* d_in, const int* in_sizes, int n_in,
                              void* d_out, int out_size)
{
    const float* points = (const float*)d_in[0];  // [1, n_points]
    const float* theta  = (const float*)d_in[1];  // [n_theta, 30]
    const float* basis  = (const float*)d_in[2];  // [64, 30]
    float* out = (float*)d_out;                   // [n_theta, 1, n_points]

    const int n_points = in_sizes[0];
    const int n_theta  = in_sizes[1] / DDIM;

    dim3 grid((n_points + BLOCK * PPT - 1) / (BLOCK * PPT), n_theta);
    cpab_kernel<<<grid, BLOCK>>>(points, theta, basis, out, n_points);
}